// round 7
// baseline (speedup 1.0000x reference)
#include <cuda_runtime.h>
#include <cstdint>

#define NQ   4
#define DIM  16
#define NL   2
#define EDIM 512
#define E4   128
#define NTHREADS 128
#define NWARPS 4
#define TOK  2
#define NTOKENS (512*128)
#define NTILES (NTOKENS / TOK)        // 32768
#define GRID 592                       // 4 blocks/SM exactly
#define STRIDE (GRID*NWARPS)           // 2368

typedef unsigned long long ull;

__device__ __forceinline__ ull pack2(float lo, float hi) {
    ull r; asm("mov.b64 %0, {%1,%2};" : "=l"(r) : "f"(lo), "f"(hi)); return r;
}
__device__ __forceinline__ ull dup2(float v) {
    ull r; asm("mov.b64 %0, {%1,%1};" : "=l"(r) : "f"(v)); return r;
}
__device__ __forceinline__ void unpack2(ull p, float& lo, float& hi) {
    asm("mov.b64 {%0,%1}, %2;" : "=f"(lo), "=f"(hi) : "l"(p));
}
__device__ __forceinline__ ull ffma2(ull a, ull b, ull c) {
    ull d; asm("fma.rn.f32x2 %0, %1, %2, %3;" : "=l"(d) : "l"(a), "l"(b), "l"(c));
    return d;
}
__device__ __forceinline__ void stcs2x64(void* p, ull a, ull b) {
    asm volatile("st.global.cs.v2.b64 [%0], {%1,%2};" :: "l"(p), "l"(a), "l"(b) : "memory");
}

__global__ __launch_bounds__(NTHREADS, 4)
void qlayer_fused(const float* __restrict__ x,
                  const float* __restrict__ qw,
                  const float* __restrict__ Wq,
                  const float* __restrict__ bq,
                  const float* __restrict__ Wc,
                  const float* __restrict__ bc,
                  float* __restrict__ out)
{
    __shared__ float4 sWq[NQ][E4];     // conflict-free: lane stride 16B
    __shared__ float4 sWcT[NQ][E4];    // Wc transposed [q][e4], conflict-free
    __shared__ float4 sbc4[E4];
    __shared__ float2 sdiag[NL][DIM];
    __shared__ float2 srys[NL][NQ];
    __shared__ float  sbq[NQ];

    const int tid  = threadIdx.x;
    const int lane = tid & 31;
    const int warp = tid >> 5;

    // ---- Stage weights / constants ----
    for (int i = tid; i < NQ*E4; i += NTHREADS)
        ((float4*)sWq)[i] = ((const float4*)Wq)[i];
    {
        float* f = (float*)sWcT;
        for (int e = tid; e < EDIM; e += NTHREADS) {
            float4 r = ((const float4*)Wc)[e];
            f[0*EDIM+e] = r.x; f[1*EDIM+e] = r.y;
            f[2*EDIM+e] = r.z; f[3*EDIM+e] = r.w;
        }
    }
    for (int i = tid; i < E4; i += NTHREADS)
        sbc4[i] = ((const float4*)bc)[i];
    if (tid < NQ) sbq[tid] = bq[tid];

    if (tid < NL*DIM) {                // fused CRZ-ring diagonal
        int l = tid >> 4, k = tid & 15;
        float ang = 0.f;
        #pragma unroll
        for (int i = 0; i < NQ; i++) {
            int cb = (k >> (NQ-1-i)) & 1;
            int tb = (k >> (NQ-1-((i+1)&(NQ-1)))) & 1;
            if (cb) ang += 0.5f * qw[l*2*NQ + i] * (float)(2*tb - 1);
        }
        float sn, cs; sincosf(ang, &sn, &cs);
        sdiag[l][k] = make_float2(cs, sn);
    }
    if (tid >= 32 && tid < 32 + NL*NQ) {
        int t = tid - 32, l = t >> 2, i = t & 3;
        float sn, cs; sincosf(0.5f * qw[l*2*NQ + NQ + i], &sn, &cs);
        srys[l][i] = make_float2(cs, sn);
    }
    __syncthreads();

    const float bq0 = sbq[0], bq1 = sbq[1], bq2 = sbq[2], bq3 = sbq[3];
    const float4* __restrict__ x4 = (const float4*)x;
    float4* __restrict__ out4 = (float4*)out;

    const int gwid = blockIdx.x * NWARPS + warp;

    float4 xbuf[8];     // 2 tokens x 4 chunks
    ull acc[8];         // packed e-pair partials, index t*4+q

    // -------- helpers as macros (stay in one basic block) --------
#define LOAD_TILE(TI) do {                                              \
        const size_t _b = (size_t)(TI) * TOK * E4 + lane;               \
        _Pragma("unroll")                                               \
        for (int _t = 0; _t < TOK; _t++)                                \
            _Pragma("unroll")                                           \
            for (int _c = 0; _c < 4; _c++)                              \
                xbuf[_t*4+_c] = __ldcs(&x4[_b + (size_t)_t*E4 + _c*32]);\
    } while (0)

#define CONSUME(ACC) do {                                               \
        _Pragma("unroll")                                               \
        for (int _i = 0; _i < 8; _i++) (ACC)[_i] = 0ull;                \
        _Pragma("unroll")                                               \
        for (int _c = 0; _c < 4; _c++) {                                \
            const int _j4 = _c*32 + lane;                               \
            const ulonglong2 _w0 = *(const ulonglong2*)&sWq[0][_j4];    \
            const ulonglong2 _w1 = *(const ulonglong2*)&sWq[1][_j4];    \
            const ulonglong2 _w2 = *(const ulonglong2*)&sWq[2][_j4];    \
            const ulonglong2 _w3 = *(const ulonglong2*)&sWq[3][_j4];    \
            _Pragma("unroll")                                           \
            for (int _t = 0; _t < TOK; _t++) {                          \
                float4 _xv = xbuf[_t*4+_c];                             \
                ull _xl = pack2(_xv.x, _xv.y);                          \
                ull _xh = pack2(_xv.z, _xv.w);                          \
                (ACC)[_t*4+0] = ffma2(_xl, _w0.x, ffma2(_xh, _w0.y, (ACC)[_t*4+0])); \
                (ACC)[_t*4+1] = ffma2(_xl, _w1.x, ffma2(_xh, _w1.y, (ACC)[_t*4+1])); \
                (ACC)[_t*4+2] = ffma2(_xl, _w2.x, ffma2(_xh, _w2.y, (ACC)[_t*4+2])); \
                (ACC)[_t*4+3] = ffma2(_xl, _w3.x, ffma2(_xh, _w3.y, (ACC)[_t*4+3])); \
            }                                                           \
        }                                                               \
    } while (0)

    // ---- Prologue: tile0 loaded+consumed, tile1 loading ----
    int tile = gwid;
    LOAD_TILE(tile);
    CONSUME(acc);
    {
        int nt = tile + STRIDE; if (nt > NTILES-1) nt = NTILES-1;
        LOAD_TILE(nt);
    }

    #pragma unroll 1
    for (; tile < NTILES; tile += STRIDE) {
        // ---- (A) consume tile+STRIDE (indep of tree/circuit below) ----
        ull accN[8];
        CONSUME(accN);
        int pf = tile + 2*STRIDE; if (pf > NTILES-1) pf = NTILES-1;
        LOAD_TILE(pf);

        // ---- (B) tree reduction on acc: 8 partial-pairs -> scalar sums ----
        float v8[8];
        #pragma unroll
        for (int i = 0; i < 8; i++) {
            float lo, hi; unpack2(acc[i], lo, hi);
            v8[i] = lo + hi;
        }
        float v4_[4];
        {
            const bool hi = (lane & 16) != 0;
            #pragma unroll
            for (int i = 0; i < 4; i++) {
                float mine = hi ? v8[i+4] : v8[i];
                float send = hi ? v8[i]   : v8[i+4];
                v4_[i] = mine + __shfl_xor_sync(0xffffffffu, send, 16);
            }
        }
        float v2_[2];
        {
            const bool hi = (lane & 8) != 0;
            #pragma unroll
            for (int i = 0; i < 2; i++) {
                float mine = hi ? v4_[i+2] : v4_[i];
                float send = hi ? v4_[i]   : v4_[i+2];
                v2_[i] = mine + __shfl_xor_sync(0xffffffffu, send, 8);
            }
        }
        float v1;
        {
            const bool hi = (lane & 4) != 0;
            float mine = hi ? v2_[1] : v2_[0];
            float send = hi ? v2_[0] : v2_[1];
            v1 = mine + __shfl_xor_sync(0xffffffffu, send, 4);
        }
        v1 += __shfl_xor_sync(0xffffffffu, v1, 2);
        v1 += __shfl_xor_sync(0xffffffffu, v1, 1);
        // value index v = 4t+q with t=bit4(lane), q=bits3..2(lane)
        const int tl = lane & 1;               // this lane's token
        float gx = __shfl_sync(0xffffffffu, v1, 16*tl + 0);
        float gy = __shfl_sync(0xffffffffu, v1, 16*tl + 4);
        float gz = __shfl_sync(0xffffffffu, v1, 16*tl + 8);
        float gw = __shfl_sync(0xffffffffu, v1, 16*tl + 12);

        // ---- (C) circuit: branchless, all 32 lanes (token = lane&1) ----
        float z0 = 0.f, z1 = 0.f, z2 = 0.f, z3 = 0.f;
        {
            float c_[4], s_[4];
            __sincosf(0.5f*(gx + bq0), &s_[0], &c_[0]);
            __sincosf(0.5f*(gy + bq1), &s_[1], &c_[1]);
            __sincosf(0.5f*(gz + bq2), &s_[2], &c_[2]);
            __sincosf(0.5f*(gw + bq3), &s_[3], &c_[3]);

            float2 st[DIM];
            #pragma unroll
            for (int k = 0; k < DIM; k++) {
                float m = 1.f; int p = 0;
                #pragma unroll
                for (int w = 0; w < NQ; w++) {
                    if ((k >> (NQ-1-w)) & 1) { m *= s_[w]; p++; }
                    else                     { m *= c_[w]; }
                }
                float re, im;
                switch (p & 3) {
                    case 0:  re =  m; im = 0.f; break;
                    case 1:  re = 0.f; im = -m; break;
                    case 2:  re = -m; im = 0.f; break;
                    default: re = 0.f; im =  m; break;
                }
                st[k] = make_float2(re, im);
            }
            #pragma unroll
            for (int l = 0; l < NL; l++) {
                #pragma unroll
                for (int k = 0; k < DIM; k++) {
                    float2 d = sdiag[l][k];
                    float re = st[k].x*d.x - st[k].y*d.y;
                    float im = st[k].x*d.y + st[k].y*d.x;
                    st[k].x = re; st[k].y = im;
                }
                #pragma unroll
                for (int i = 0; i < NQ; i++) {
                    float2 cs = srys[l][i];
                    const int S = 1 << (NQ-1-i);
                    #pragma unroll
                    for (int k = 0; k < DIM; k++) {
                        if (k & S) continue;
                        float2 a0 = st[k], a1 = st[k|S];
                        st[k].x   = cs.x*a0.x - cs.y*a1.x;
                        st[k].y   = cs.x*a0.y - cs.y*a1.y;
                        st[k|S].x = cs.y*a0.x + cs.x*a1.x;
                        st[k|S].y = cs.y*a0.y + cs.x*a1.y;
                    }
                }
            }
            #pragma unroll
            for (int k = 0; k < DIM; k++) {
                float p = st[k].x*st[k].x + st[k].y*st[k].y;
                z0 += (k & 8) ? -p : p;
                z1 += (k & 4) ? -p : p;
                z2 += (k & 2) ? -p : p;
                z3 += (k & 1) ? -p : p;
            }
        }

        // ---- broadcast q_out (lane m holds token m for m in {0,1}) ----
        ull dqx[TOK], dqy[TOK], dqz[TOK], dqe[TOK];
        #pragma unroll
        for (int m = 0; m < TOK; m++) {
            dqx[m] = dup2(__shfl_sync(0xffffffffu, z0, m));
            dqy[m] = dup2(__shfl_sync(0xffffffffu, z1, m));
            dqz[m] = dup2(__shfl_sync(0xffffffffu, z2, m));
            dqe[m] = dup2(__shfl_sync(0xffffffffu, z3, m));
        }

        // ---- (D) store: packed out = q_out . Wc^T + bc ----
        const size_t obase = (size_t)tile * TOK * E4;
        #pragma unroll
        for (int c = 0; c < 4; c++) {
            const int e4 = c*32 + lane;
            const ulonglong2 w0 = ((const ulonglong2*)sWcT[0])[e4];
            const ulonglong2 w1 = ((const ulonglong2*)sWcT[1])[e4];
            const ulonglong2 w2 = ((const ulonglong2*)sWcT[2])[e4];
            const ulonglong2 w3 = ((const ulonglong2*)sWcT[3])[e4];
            const ulonglong2 bb = ((const ulonglong2*)sbc4)[e4];
            #pragma unroll
            for (int m = 0; m < TOK; m++) {
                ull axy = bb.x, azw = bb.y;
                axy = ffma2(dqx[m], w0.x, axy);  azw = ffma2(dqx[m], w0.y, azw);
                axy = ffma2(dqy[m], w1.x, axy);  azw = ffma2(dqy[m], w1.y, azw);
                axy = ffma2(dqz[m], w2.x, axy);  azw = ffma2(dqz[m], w2.y, azw);
                axy = ffma2(dqe[m], w3.x, axy);  azw = ffma2(dqe[m], w3.y, azw);
                stcs2x64(&out4[obase + (size_t)m*E4 + e4], axy, azw);
            }
        }

        // ---- rotate pipeline ----
        #pragma unroll
        for (int i = 0; i < 8; i++) acc[i] = accN[i];
    }
#undef LOAD_TILE
#undef CONSUME
}

extern "C" void kernel_launch(void* const* d_in, const int* in_sizes, int n_in,
                              void* d_out, int out_size) {
    const float* x  = (const float*)d_in[0];
    const float* qw = (const float*)d_in[1];
    const float* Wq = (const float*)d_in[2];
    const float* bq = (const float*)d_in[3];
    const float* Wc = (const float*)d_in[4];
    const float* bc = (const float*)d_in[5];
    float* out = (float*)d_out;

    qlayer_fused<<<GRID, NTHREADS>>>(x, qw, Wq, bq, Wc, bc, out);
}

// round 8
// speedup vs baseline: 1.0396x; 1.0396x over previous
#include <cuda_runtime.h>
#include <cstdint>

#define NQ   4
#define DIM  16
#define NL   2
#define EDIM 512
#define E4   128
#define NTHREADS 128
#define NWARPS 4
#define TOK  4
#define NTOKENS (512*128)
#define NTILES (NTOKENS / TOK)        // 16384
#define GRID 592                       // 4 blocks/SM exactly
#define STRIDE (GRID*NWARPS)           // 2368

typedef unsigned long long ull;

__device__ __forceinline__ ull pack2(float lo, float hi) {
    ull r; asm("mov.b64 %0, {%1,%2};" : "=l"(r) : "f"(lo), "f"(hi)); return r;
}
__device__ __forceinline__ ull dup2(float v) {
    ull r; asm("mov.b64 %0, {%1,%1};" : "=l"(r) : "f"(v)); return r;
}
__device__ __forceinline__ void unpack2(ull p, float& lo, float& hi) {
    asm("mov.b64 {%0,%1}, %2;" : "=f"(lo), "=f"(hi) : "l"(p));
}
__device__ __forceinline__ ull ffma2(ull a, ull b, ull c) {
    ull d; asm("fma.rn.f32x2 %0, %1, %2, %3;" : "=l"(d) : "l"(a), "l"(b), "l"(c));
    return d;
}
__device__ __forceinline__ void stcs2x64(void* p, ull a, ull b) {
    asm volatile("st.global.cs.v2.b64 [%0], {%1,%2};" :: "l"(p), "l"(a), "l"(b) : "memory");
}

__global__ __launch_bounds__(NTHREADS, 4)
void qlayer_fused(const float* __restrict__ x,
                  const float* __restrict__ qw,
                  const float* __restrict__ Wq,
                  const float* __restrict__ bq,
                  const float* __restrict__ Wc,
                  const float* __restrict__ bc,
                  float* __restrict__ out)
{
    __shared__ float4 sWq[NQ][E4];     // [q][e4]: lane stride 16B, conflict-free
    __shared__ float4 sWcT[NQ][E4];    // Wc transposed [q][e4], conflict-free
    __shared__ float4 sbc4[E4];
    __shared__ float2 sdiag[NL][DIM];  // fused CRZ-ring diagonal
    __shared__ float2 srys[NL][NQ];
    __shared__ float  sbq[NQ];

    const int tid  = threadIdx.x;
    const int lane = tid & 31;
    const int warp = tid >> 5;

    // ---- Stage weights / constants ----
    for (int i = tid; i < NQ*E4; i += NTHREADS)
        ((float4*)sWq)[i] = ((const float4*)Wq)[i];
    {
        float* f = (float*)sWcT;
        for (int e = tid; e < EDIM; e += NTHREADS) {
            float4 r = ((const float4*)Wc)[e];
            f[0*EDIM+e] = r.x; f[1*EDIM+e] = r.y;
            f[2*EDIM+e] = r.z; f[3*EDIM+e] = r.w;
        }
    }
    for (int i = tid; i < E4; i += NTHREADS)
        sbc4[i] = ((const float4*)bc)[i];
    if (tid < NQ) sbq[tid] = bq[tid];

    if (tid < NL*DIM) {                // fused CRZ-ring diagonal
        int l = tid >> 4, k = tid & 15;
        float ang = 0.f;
        #pragma unroll
        for (int i = 0; i < NQ; i++) {
            int cb = (k >> (NQ-1-i)) & 1;
            int tb = (k >> (NQ-1-((i+1)&(NQ-1)))) & 1;
            if (cb) ang += 0.5f * qw[l*2*NQ + i] * (float)(2*tb - 1);
        }
        float sn, cs; sincosf(ang, &sn, &cs);
        sdiag[l][k] = make_float2(cs, sn);
    }
    if (tid >= 32 && tid < 32 + NL*NQ) {
        int t = tid - 32, l = t >> 2, i = t & 3;
        float sn, cs; sincosf(0.5f * qw[l*2*NQ + NQ + i], &sn, &cs);
        srys[l][i] = make_float2(cs, sn);
    }
    __syncthreads();

    const float bq0 = sbq[0], bq1 = sbq[1], bq2 = sbq[2], bq3 = sbq[3];
    const float4* __restrict__ x4 = (const float4*)x;
    float4* __restrict__ out4 = (float4*)out;

    const int gwid = blockIdx.x * NWARPS + warp;

    float4 xbuf[16];    // 4 tokens x 4 chunks: pipeline buffer

    // ---- Prologue: load first tile ----
    int tile = gwid;
    if (tile < NTILES) {
        const size_t base = (size_t)tile * TOK * E4 + lane;
        #pragma unroll
        for (int t = 0; t < TOK; t++)
            #pragma unroll
            for (int c = 0; c < 4; c++)
                xbuf[t*4+c] = __ldcs(&x4[base + (size_t)t*E4 + c*32]);
    }

    #pragma unroll 1
    for (; tile < NTILES; tile += STRIDE) {
        // ---- Consume buffer: f32x2 partial dots (frees xbuf) ----
        ull acc[16];                       // [t*4+q], packed over adjacent-e pair
        #pragma unroll
        for (int i = 0; i < 16; i++) acc[i] = 0ull;
        #pragma unroll
        for (int c = 0; c < 4; c++) {
            const int j4 = c*32 + lane;
            const ulonglong2 w0 = *(const ulonglong2*)&sWq[0][j4];
            const ulonglong2 w1 = *(const ulonglong2*)&sWq[1][j4];
            const ulonglong2 w2 = *(const ulonglong2*)&sWq[2][j4];
            const ulonglong2 w3 = *(const ulonglong2*)&sWq[3][j4];
            #pragma unroll
            for (int t = 0; t < TOK; t++) {
                float4 xv = xbuf[t*4+c];
                ull xl = pack2(xv.x, xv.y);
                ull xh = pack2(xv.z, xv.w);
                acc[t*4+0] = ffma2(xl, w0.x, ffma2(xh, w0.y, acc[t*4+0]));
                acc[t*4+1] = ffma2(xl, w1.x, ffma2(xh, w1.y, acc[t*4+1]));
                acc[t*4+2] = ffma2(xl, w2.x, ffma2(xh, w2.y, acc[t*4+2]));
                acc[t*4+3] = ffma2(xl, w3.x, ffma2(xh, w3.y, acc[t*4+3]));
            }
        }

        // ---- Prefetch next tile NOW (in flight during shfl+circuit+store) ----
        {
            int nxt = tile + STRIDE; if (nxt > NTILES-1) nxt = NTILES-1;
            const size_t base = (size_t)nxt * TOK * E4 + lane;
            #pragma unroll
            for (int t = 0; t < TOK; t++)
                #pragma unroll
                for (int c = 0; c < 4; c++)
                    xbuf[t*4+c] = __ldcs(&x4[base + (size_t)t*E4 + c*32]);
        }

        // ---- Horizontal add of pairs, then tree reduction 16 -> 1/lane ----
        float v16[16];
        #pragma unroll
        for (int i = 0; i < 16; i++) {
            float lo, hi; unpack2(acc[i], lo, hi);
            v16[i] = lo + hi;
        }
        float v8[8];
        {
            const bool hi = (lane & 16) != 0;
            #pragma unroll
            for (int i = 0; i < 8; i++) {
                float mine = hi ? v16[i+8] : v16[i];
                float send = hi ? v16[i]   : v16[i+8];
                v8[i] = mine + __shfl_xor_sync(0xffffffffu, send, 16);
            }
        }
        float v4_[4];
        {
            const bool hi = (lane & 8) != 0;
            #pragma unroll
            for (int i = 0; i < 4; i++) {
                float mine = hi ? v8[i+4] : v8[i];
                float send = hi ? v8[i]   : v8[i+4];
                v4_[i] = mine + __shfl_xor_sync(0xffffffffu, send, 8);
            }
        }
        float v2_[2];
        {
            const bool hi = (lane & 4) != 0;
            #pragma unroll
            for (int i = 0; i < 2; i++) {
                float m2 = hi ? v4_[i+2] : v4_[i];
                float s2 = hi ? v4_[i]   : v4_[i+2];
                v2_[i] = m2 + __shfl_xor_sync(0xffffffffu, s2, 4);
            }
        }
        float v1;
        {
            const bool hi = (lane & 2) != 0;
            float mine = hi ? v2_[1] : v2_[0];
            float send = hi ? v2_[0] : v2_[1];
            v1 = mine + __shfl_xor_sync(0xffffffffu, send, 2);
        }
        v1 += __shfl_xor_sync(0xffffffffu, v1, 1);
        // lane L holds (t = L>>3, q = 2*((L>>2)&1)+((L>>1)&1)); gather tokens -> lanes 0..3
        const int tl = lane & 3;
        float gx  = __shfl_sync(0xffffffffu, v1, 8*tl + 0);
        float gy  = __shfl_sync(0xffffffffu, v1, 8*tl + 2);
        float gz  = __shfl_sync(0xffffffffu, v1, 8*tl + 4);
        float gw_ = __shfl_sync(0xffffffffu, v1, 8*tl + 6);

        // ---- Circuit on lanes 0..3 (one token per lane) ----
        float z0 = 0.f, z1 = 0.f, z2 = 0.f, z3 = 0.f;
        if (lane < TOK) {
            float c_[4], s_[4];
            __sincosf(0.5f*(gx + bq0),  &s_[0], &c_[0]);
            __sincosf(0.5f*(gy + bq1),  &s_[1], &c_[1]);
            __sincosf(0.5f*(gz + bq2),  &s_[2], &c_[2]);
            __sincosf(0.5f*(gw_ + bq3), &s_[3], &c_[3]);

            float2 st[DIM];
            #pragma unroll
            for (int k = 0; k < DIM; k++) {
                float m = 1.f; int p = 0;
                #pragma unroll
                for (int w = 0; w < NQ; w++) {
                    if ((k >> (NQ-1-w)) & 1) { m *= s_[w]; p++; }
                    else                     { m *= c_[w]; }
                }
                float re, im;
                switch (p & 3) {
                    case 0:  re =  m; im = 0.f; break;
                    case 1:  re = 0.f; im = -m; break;
                    case 2:  re = -m; im = 0.f; break;
                    default: re = 0.f; im =  m; break;
                }
                st[k] = make_float2(re, im);
            }
            #pragma unroll
            for (int l = 0; l < NL; l++) {
                #pragma unroll
                for (int k = 0; k < DIM; k++) {
                    float2 d = sdiag[l][k];
                    float re = st[k].x*d.x - st[k].y*d.y;
                    float im = st[k].x*d.y + st[k].y*d.x;
                    st[k].x = re; st[k].y = im;
                }
                #pragma unroll
                for (int i = 0; i < NQ; i++) {
                    float2 cs = srys[l][i];
                    const int S = 1 << (NQ-1-i);
                    #pragma unroll
                    for (int k = 0; k < DIM; k++) {
                        if (k & S) continue;
                        float2 a0 = st[k], a1 = st[k|S];
                        st[k].x   = cs.x*a0.x - cs.y*a1.x;
                        st[k].y   = cs.x*a0.y - cs.y*a1.y;
                        st[k|S].x = cs.y*a0.x + cs.x*a1.x;
                        st[k|S].y = cs.y*a0.y + cs.x*a1.y;
                    }
                }
            }
            #pragma unroll
            for (int k = 0; k < DIM; k++) {
                float p = st[k].x*st[k].x + st[k].y*st[k].y;
                z0 += (k & 8) ? -p : p;
                z1 += (k & 4) ? -p : p;
                z2 += (k & 2) ? -p : p;
                z3 += (k & 1) ? -p : p;
            }
        }

        // ---- Broadcast q_out once (lane m holds token m, m in 0..3) ----
        ull dqx[TOK], dqy[TOK], dqz[TOK], dqe[TOK];
        #pragma unroll
        for (int m = 0; m < TOK; m++) {
            dqx[m] = dup2(__shfl_sync(0xffffffffu, z0, m));
            dqy[m] = dup2(__shfl_sync(0xffffffffu, z1, m));
            dqz[m] = dup2(__shfl_sync(0xffffffffu, z2, m));
            dqe[m] = dup2(__shfl_sync(0xffffffffu, z3, m));
        }

        // ---- Phase 3: packed out = q_out . Wc^T + bc ----
        const size_t obase = (size_t)tile * TOK * E4;
        #pragma unroll
        for (int c = 0; c < 4; c++) {
            const int e4 = c*32 + lane;
            const ulonglong2 w0 = ((const ulonglong2*)sWcT[0])[e4];
            const ulonglong2 w1 = ((const ulonglong2*)sWcT[1])[e4];
            const ulonglong2 w2 = ((const ulonglong2*)sWcT[2])[e4];
            const ulonglong2 w3 = ((const ulonglong2*)sWcT[3])[e4];
            const ulonglong2 bb = ((const ulonglong2*)sbc4)[e4];
            #pragma unroll
            for (int m = 0; m < TOK; m++) {
                ull axy = bb.x, azw = bb.y;
                axy = ffma2(dqx[m], w0.x, axy);  azw = ffma2(dqx[m], w0.y, azw);
                axy = ffma2(dqy[m], w1.x, axy);  azw = ffma2(dqy[m], w1.y, azw);
                axy = ffma2(dqz[m], w2.x, axy);  azw = ffma2(dqz[m], w2.y, azw);
                axy = ffma2(dqe[m], w3.x, axy);  azw = ffma2(dqe[m], w3.y, azw);
                stcs2x64(&out4[obase + (size_t)m*E4 + e4], axy, azw);
            }
        }
    }
}

extern "C" void kernel_launch(void* const* d_in, const int* in_sizes, int n_in,
                              void* d_out, int out_size) {
    const float* x  = (const float*)d_in[0];
    const float* qw = (const float*)d_in[1];
    const float* Wq = (const float*)d_in[2];
    const float* bq = (const float*)d_in[3];
    const float* Wc = (const float*)d_in[4];
    const float* bc = (const float*)d_in[5];
    float* out = (float*)d_out;

    qlayer_fused<<<GRID, NTHREADS>>>(x, qw, Wq, bq, Wc, bc, out);
}